// round 1
// baseline (speedup 1.0000x reference)
#include <cuda_runtime.h>
#include <cstdint>

#define N_NODES   100000
#define N_EDGES   800000
#define HIDF      128
#define EMBF      64
#define OUTF      8
#define N_GRAPHS  64

// ---------------- scratch (device globals; no allocation) ----------------
__device__ int   g_is64;
__device__ int   g_src[N_EDGES];
__device__ int   g_dst[N_EDGES];
__device__ int   g_batch[N_NODES];
__device__ int   g_deg[N_NODES];
__device__ int   g_off[N_NODES];
__device__ int   g_cur[N_NODES];
__device__ int   g_csr[N_EDGES];
__device__ float g_agg[(size_t)N_NODES * HIDF];
__device__ float g_h1 [(size_t)N_NODES * HIDF];
__device__ float g_h2 [(size_t)N_NODES * HIDF];
__device__ float g_wc1[256 * HIDF];
__device__ float g_wc2[256 * HIDF];
__device__ float g_pool[N_GRAPHS * HIDF];
__device__ int   g_cnt[N_GRAPHS];

// ---------------- dtype detection (int64 vs int32 indices) ----------------
// Values are node ids in [0, 100000). If stored as int64 (little-endian),
// every odd 32-bit word is 0. If int32, odd words are random ids (P(all
// zero) ~ 0). Checks the first 4096 words of edge_index.
__global__ void k_detect(const unsigned int* __restrict__ w) {
    __shared__ int flag;
    if (threadIdx.x == 0) flag = 0;
    __syncthreads();
    for (int i = 1 + (int)threadIdx.x * 2; i < 4096; i += blockDim.x * 2)
        if (w[i] != 0u) atomicOr(&flag, 1);
    __syncthreads();
    if (threadIdx.x == 0) g_is64 = (flag == 0) ? 1 : 0;
}

__global__ void k_convert_edges(const void* __restrict__ ei) {
    int i = blockIdx.x * blockDim.x + threadIdx.x;
    if (i >= N_EDGES) return;
    if (g_is64) {
        const long long* p = (const long long*)ei;
        g_src[i] = (int)p[i];
        g_dst[i] = (int)p[N_EDGES + i];
    } else {
        const int* p = (const int*)ei;
        g_src[i] = p[i];
        g_dst[i] = p[N_EDGES + i];
    }
}

// Also zeroes deg / pool / cnt (stream-ordered before hist & pool use).
__global__ void k_convert_batch(const void* __restrict__ b) {
    int i = blockIdx.x * blockDim.x + threadIdx.x;
    if (i >= N_NODES) return;
    if (g_is64) g_batch[i] = (int)((const long long*)b)[i];
    else        g_batch[i] = ((const int*)b)[i];
    g_deg[i] = 0;
    if (i < N_GRAPHS * HIDF) g_pool[i] = 0.f;
    if (i < N_GRAPHS)        g_cnt[i]  = 0;
}

// ---------------- CSR build ----------------
__global__ void k_hist() {
    int i = blockIdx.x * blockDim.x + threadIdx.x;
    if (i < N_EDGES) atomicAdd(&g_deg[g_dst[i]], 1);
}

__global__ void k_scan() {  // one block, 1024 threads
    __shared__ int ssum[1024];
    const int CH = 98;  // 1024*98 = 100352 >= 100000
    int t = threadIdx.x;
    int lo = t * CH, hi = min(lo + CH, N_NODES);
    int s = 0;
    for (int i = lo; i < hi; i++) s += g_deg[i];
    ssum[t] = s;
    __syncthreads();
    for (int o = 1; o < 1024; o <<= 1) {
        int v = (t >= o) ? ssum[t - o] : 0;
        __syncthreads();
        ssum[t] += v;
        __syncthreads();
    }
    int base = ssum[t] - s;   // exclusive prefix
    for (int i = lo; i < hi; i++) {
        g_off[i] = base;
        g_cur[i] = base;
        base += g_deg[i];
    }
}

__global__ void k_fill() {
    int i = blockIdx.x * blockDim.x + threadIdx.x;
    if (i >= N_EDGES) return;
    int d = g_dst[i];
    int p = atomicAdd(&g_cur[d], 1);
    g_csr[p] = g_src[i];
}

// ---------------- mean aggregation: one warp per node ----------------
__global__ void k_aggregate(const float* __restrict__ H, float* __restrict__ A) {
    int node = (blockIdx.x * blockDim.x + threadIdx.x) >> 5;
    int lane = threadIdx.x & 31;
    if (node >= N_NODES) return;
    int start = g_off[node];
    int d = g_deg[node];
    float4 acc = make_float4(0.f, 0.f, 0.f, 0.f);
    for (int e = 0; e < d; e++) {
        int s = g_csr[start + e];
        float4 v = ((const float4*)(H + (size_t)s * HIDF))[lane];
        acc.x += v.x; acc.y += v.y; acc.z += v.z; acc.w += v.w;
    }
    float inv = 1.0f / (float)max(d, 1);
    acc.x *= inv; acc.y *= inv; acc.z *= inv; acc.w *= inv;
    ((float4*)(A + (size_t)node * HIDF))[lane] = acc;
}

// ---------------- weight concat (K-major [256][128]) ----------------
__global__ void k_prep(const float* __restrict__ W1l, const float* __restrict__ W1r,
                       const float* __restrict__ W2l, const float* __restrict__ W2r,
                       float* __restrict__ wc1, float* __restrict__ wc2) {
    int idx = blockIdx.x * blockDim.x + threadIdx.x;
    if (idx >= 256 * HIDF) return;
    int k = idx >> 7, j = idx & 127;
    wc1[idx] = (k < 128) ? W1l[j * 128 + k] : W1r[j * 128 + (k - 128)];
    wc2[idx] = (k < 128) ? W2l[j * 128 + k] : W2r[j * 128 + (k - 128)];
}

// ---------------- fused GEMM: relu(agg@Wl^T + h@Wr^T + b) ----------------
// M=100000, N=128, K=256 (cols 0-127 from Agg, 128-255 from Hin).
// BM=128, BN=128, BK=16, 256 threads, 8x8 per-thread tile.
__global__ void __launch_bounds__(256)
k_gemm(const float* __restrict__ Agg, const float* __restrict__ Hin,
       const float* __restrict__ Wc, const float* __restrict__ bias,
       float* __restrict__ Hout) {
    __shared__ float As[16][128];
    __shared__ float Bs[16][128];
    __shared__ float bsh[128];
    int tid = threadIdx.x;
    int row0 = blockIdx.x * 128;
    if (tid < 128) bsh[tid] = bias[tid];
    int ty = tid >> 4, tx = tid & 15;
    float acc[8][8];
#pragma unroll
    for (int i = 0; i < 8; i++)
#pragma unroll
        for (int j = 0; j < 8; j++) acc[i][j] = 0.f;

    for (int k0 = 0; k0 < 256; k0 += 16) {
        const float* S = (k0 < 128) ? Agg : Hin;
        int kc = k0 & 127;
        // A tile: 128 rows x 16 k, stored transposed As[k][m]
        {
            int r = tid >> 2;
            int c = (tid & 3) * 4;
#pragma unroll
            for (int rr = 0; rr < 2; rr++) {
                int row = row0 + r + rr * 64;
                float4 v = make_float4(0.f, 0.f, 0.f, 0.f);
                if (row < N_NODES)
                    v = *(const float4*)(S + (size_t)row * HIDF + kc + c);
                As[c + 0][r + rr * 64] = v.x;
                As[c + 1][r + rr * 64] = v.y;
                As[c + 2][r + rr * 64] = v.z;
                As[c + 3][r + rr * 64] = v.w;
            }
        }
        // B tile: 16 k x 128 cols
        {
            int kk = tid >> 5;
            int j = (tid & 31) * 4;
#pragma unroll
            for (int r2 = 0; r2 < 2; r2++) {
                float4 v = *(const float4*)(Wc + (size_t)(k0 + kk + r2 * 8) * HIDF + j);
                *(float4*)&Bs[kk + r2 * 8][j] = v;
            }
        }
        __syncthreads();
#pragma unroll
        for (int kk = 0; kk < 16; kk++) {
            float a[8], b[8];
#pragma unroll
            for (int i = 0; i < 8; i++) a[i] = As[kk][ty * 8 + i];
#pragma unroll
            for (int j = 0; j < 8; j++) b[j] = Bs[kk][tx * 8 + j];
#pragma unroll
            for (int i = 0; i < 8; i++)
#pragma unroll
                for (int j = 0; j < 8; j++) acc[i][j] += a[i] * b[j];
        }
        __syncthreads();
    }
#pragma unroll
    for (int i = 0; i < 8; i++) {
        int row = row0 + ty * 8 + i;
        if (row < N_NODES) {
#pragma unroll
            for (int j4 = 0; j4 < 2; j4++) {
                float4 o;
                int jb = tx * 8 + j4 * 4;
                o.x = fmaxf(acc[i][j4 * 4 + 0] + bsh[jb + 0], 0.f);
                o.y = fmaxf(acc[i][j4 * 4 + 1] + bsh[jb + 1], 0.f);
                o.z = fmaxf(acc[i][j4 * 4 + 2] + bsh[jb + 2], 0.f);
                o.w = fmaxf(acc[i][j4 * 4 + 3] + bsh[jb + 3], 0.f);
                *(float4*)(Hout + (size_t)row * HIDF + jb) = o;
            }
        }
    }
}

// ---------------- sorted segment-mean pooling ----------------
// 128 threads (one per feature), each block covers 512 nodes; batch is
// sorted so we flush one atomic per graph-change per feature.
__global__ void k_pool(const float* __restrict__ H) {
    int t = threadIdx.x;
    int base = blockIdx.x * 512;
    if (base >= N_NODES) return;
    int end = min(base + 512, N_NODES);
    int cur = g_batch[base];
    float acc = 0.f;
    int run = 0;
    for (int n = base; n < end; n++) {
        int g = g_batch[n];
        if (g != cur) {
            atomicAdd(&g_pool[cur * HIDF + t], acc);
            if (t == 0) atomicAdd(&g_cnt[cur], run);
            acc = 0.f; run = 0; cur = g;
        }
        acc += H[(size_t)n * HIDF + t];
        run++;
    }
    atomicAdd(&g_pool[cur * HIDF + t], acc);
    if (t == 0) atomicAdd(&g_cnt[cur], run);
}

// ---------------- head: z = [pooled/cnt | embed] @ Wlin^T + blin ----------------
__global__ void k_head(const float* __restrict__ embed, const float* __restrict__ Wlin,
                       const float* __restrict__ blin, float* __restrict__ out) {
    int t = threadIdx.x;
    if (t >= N_GRAPHS * OUTF) return;
    int g = t >> 3, o = t & 7;
    float c = (float)max(g_cnt[g], 1);
    float inv = 1.0f / c;
    const float* wr = Wlin + o * (HIDF + EMBF);
    float s = 0.f;
    for (int k = 0; k < HIDF; k++) s += g_pool[g * HIDF + k] * inv * wr[k];
    for (int k = 0; k < EMBF; k++) s += embed[g * EMBF + k] * wr[HIDF + k];
    out[g * OUTF + o] = s + blin[o];
}

// ---------------- launch ----------------
extern "C" void kernel_launch(void* const* d_in, const int* in_sizes, int n_in,
                              void* d_out, int out_size) {
    const float* x     = (const float*)d_in[0];
    const void*  ei    = d_in[1];
    const void*  batch = d_in[2];
    const float* embed = (const float*)d_in[3];
    const float* W1l   = (const float*)d_in[4];
    const float* b1l   = (const float*)d_in[5];
    const float* W1r   = (const float*)d_in[6];
    const float* W2l   = (const float*)d_in[7];
    const float* b2l   = (const float*)d_in[8];
    const float* W2r   = (const float*)d_in[9];
    const float* Wlin  = (const float*)d_in[10];
    const float* blin  = (const float*)d_in[11];
    float* out = (float*)d_out;

    float *agg_p, *h1_p, *h2_p, *wc1_p, *wc2_p;
    cudaGetSymbolAddress((void**)&agg_p, g_agg);
    cudaGetSymbolAddress((void**)&h1_p,  g_h1);
    cudaGetSymbolAddress((void**)&h2_p,  g_h2);
    cudaGetSymbolAddress((void**)&wc1_p, g_wc1);
    cudaGetSymbolAddress((void**)&wc2_p, g_wc2);

    const int TB = 256;
    k_detect<<<1, 256>>>((const unsigned int*)ei);
    k_convert_edges<<<(N_EDGES + TB - 1) / TB, TB>>>(ei);
    k_convert_batch<<<(N_NODES + TB - 1) / TB, TB>>>(batch);
    k_hist<<<(N_EDGES + TB - 1) / TB, TB>>>();
    k_scan<<<1, 1024>>>();
    k_fill<<<(N_EDGES + TB - 1) / TB, TB>>>();
    k_prep<<<(256 * HIDF + TB - 1) / TB, TB>>>(W1l, W1r, W2l, W2r, wc1_p, wc2_p);

    // layer 1
    k_aggregate<<<(N_NODES + 7) / 8, 256>>>(x, agg_p);
    k_gemm<<<(N_NODES + 127) / 128, 256>>>(agg_p, x, wc1_p, b1l, h1_p);
    // layer 2
    k_aggregate<<<(N_NODES + 7) / 8, 256>>>(h1_p, agg_p);
    k_gemm<<<(N_NODES + 127) / 128, 256>>>(agg_p, h1_p, wc2_p, b2l, h2_p);
    // pooling + head
    k_pool<<<(N_NODES + 511) / 512, 128>>>(h2_p);
    k_head<<<1, 512>>>(embed, Wlin, blin, out);
}